// round 15
// baseline (speedup 1.0000x reference)
#include <cuda_runtime.h>
#include <cstdint>

// Problem constants (B=2, T=2048, C=1024, H=16, hd=64, MLP width 32)
#define BSZ   2
#define TSEQ  2048
#define CDIM  1024
#define NH    16
#define HD    64
#define MLPW  32
#define UPAD  64
#define LOG2E 1.4426950408889634f

__device__ float g_qkv[3 * BSZ * NH * TSEQ * HD];   // tf32-rounded Q,K
__device__ float g_vt[BSZ * NH * HD * TSEQ];        // tf32-rounded V, TRANSPOSED [b,h][d][t]
__device__ float g_y[BSZ * TSEQ * CDIM];            // tf32-rounded attn out
__device__ float g_ut2[TSEQ + UPAD];
__device__ float g_invP[TSEQ];
__device__ float g_xr[BSZ * TSEQ * CDIM];
__device__ float g_wqkvr[CDIM * 3 * CDIM];
__device__ float g_wprojr[CDIM * CDIM];

// ===========================================================================
// Helpers
// ===========================================================================
__device__ __forceinline__ uint32_t smem_u32(const void* p) {
    uint32_t a;
    asm("{ .reg .u64 t; cvta.to.shared.u64 t, %1; cvt.u32.u64 %0, t; }"
        : "=r"(a) : "l"(p));
    return a;
}
#define CP_ASYNC16(dst, src) \
    asm volatile("cp.async.cg.shared.global [%0], [%1], 16;" \
                 :: "r"(dst), "l"(src) : "memory")
#define CP_COMMIT() asm volatile("cp.async.commit_group;" ::: "memory")
#define CP_WAIT(n)  asm volatile("cp.async.wait_group %0;" :: "n"(n) : "memory")

__device__ __forceinline__ uint32_t f2tf32(float f) {
    uint32_t r;
    asm("cvt.rna.tf32.f32 %0, %1;" : "=r"(r) : "f"(f));
    return r;
}
__device__ __forceinline__ float rnaf(float f) {
    return __uint_as_float(f2tf32(f));
}
__device__ __forceinline__ float ex2(float x) {
    float y;
    asm("ex2.approx.f32 %0, %1;" : "=f"(y) : "f"(x));
    return y;
}
__device__ __forceinline__ void mma8(float* c, const uint32_t* a,
                                     const uint32_t* b) {
    asm volatile(
        "mma.sync.aligned.m16n8k8.row.col.f32.tf32.tf32.f32 "
        "{%0,%1,%2,%3}, {%4,%5,%6,%7}, {%8,%9}, {%0,%1,%2,%3};"
        : "+f"(c[0]), "+f"(c[1]), "+f"(c[2]), "+f"(c[3])
        : "r"(a[0]), "r"(a[1]), "r"(a[2]), "r"(a[3]), "r"(b[0]), "r"(b[1]));
}
__device__ __forceinline__ void ldm_x4(uint32_t& r0, uint32_t& r1,
                                       uint32_t& r2, uint32_t& r3,
                                       uint32_t addr) {
    asm volatile(
        "ldmatrix.sync.aligned.m8n8.x4.shared.b16 {%0,%1,%2,%3}, [%4];"
        : "=r"(r0), "=r"(r1), "=r"(r2), "=r"(r3) : "r"(addr));
}

// ===========================================================================
// Init kernels
// ===========================================================================
__global__ void init_tables(const float* __restrict__ cp,
                            const float* __restrict__ lm) {
    const int i = blockIdx.x * blockDim.x + threadIdx.x;
    if (i >= TSEQ + UPAD) return;
    const float c = cp[0];
    const int   rel = i - UPAD;
    g_ut2[i] = logf(fabsf(c * (float)(rel < 0 ? 0 : rel)) + 1.0f);
    if (i < TSEQ) {
        const float thr = fabsf(lm[0] * 512.0f);
        g_invP[i] =
            1.0f / (logf(fabsf(c * fmaxf((float)i, thr)) + 1.0f) + 1e-6f);
    }
}

__global__ void cvt_tf32(const float4* __restrict__ src,
                         float4* __restrict__ dst, int n4) {
    const int i = blockIdx.x * blockDim.x + threadIdx.x;
    if (i >= n4) return;
    float4 v = src[i];
    dst[i] = make_float4(rnaf(v.x), rnaf(v.y), rnaf(v.z), rnaf(v.w));
}

// ===========================================================================
// tf32 mma.sync GEMM, 4-stage cp.async pipeline. Inputs pre-rounded (zero
// mainloop cvt). MODE 0: Q,K -> g_qkv (rounded); V -> g_vt TRANSPOSED.
// ===========================================================================
#define ABUF (128 * 20 * 4)
#define BBUF (16 * 136 * 4)
#define NSTG 4
#define GSMEM (NSTG * (ABUF + BBUF))

template <int MODE>
__global__ __launch_bounds__(256, 2) void mma_gemm(const float* __restrict__ A,
                                                   const float* __restrict__ Bm,
                                                   const float* __restrict__ bias,
                                                   float* __restrict__ out,
                                                   int K, int N) {
    extern __shared__ char sm[];
    const uint32_t sbase = smem_u32(sm);

    const int tid   = threadIdx.x;
    const int lane  = tid & 31;
    const int wid   = tid >> 5;
    const int warpM = wid & 3;
    const int warpN = wid >> 2;
    const int m0    = blockIdx.y * 128;
    const int n0    = blockIdx.x * 128;

    const int ar = tid >> 2;
    const int ak = (tid & 3) * 4;
    const float* Ag = A + (size_t)(m0 + ar) * K + ak;
    const int br = tid >> 4;
    const int bc = (tid & 15) * 4;
    const float* Bg = Bm + (size_t)br * N + n0 + bc;

    const uint32_t aOff0 = (uint32_t)(ar * 20 + ak) * 4;
    const uint32_t aOff1 = (uint32_t)((ar + 64) * 20 + ak) * 4;
    const uint32_t bOff0 = (uint32_t)(br * 136 + bc) * 4;
    const uint32_t bOff1 = (uint32_t)(br * 136 + bc + 64) * 4;

#define LOADTILE(st, kc)                                                      \
    do {                                                                      \
        const uint32_t as = sbase + (st) * ABUF;                              \
        const uint32_t bs = sbase + NSTG * ABUF + (st) * BBUF;                \
        CP_ASYNC16(as + aOff0, Ag + (kc) * 16);                               \
        CP_ASYNC16(as + aOff1, Ag + (size_t)64 * K + (kc) * 16);              \
        CP_ASYNC16(bs + bOff0, Bg + (size_t)(kc) * 16 * N);                   \
        CP_ASYNC16(bs + bOff1, Bg + (size_t)(kc) * 16 * N + 64);              \
        CP_COMMIT();                                                          \
    } while (0)

    float acc[2][8][4];
#pragma unroll
    for (int mf = 0; mf < 2; mf++)
#pragma unroll
        for (int nf = 0; nf < 8; nf++)
#pragma unroll
            for (int i = 0; i < 4; i++) acc[mf][nf][i] = 0.0f;

    const int r  = lane >> 2;
    const int cq = lane & 3;
    const int nk = K >> 4;

    LOADTILE(0, 0);
    LOADTILE(1, 1);
    LOADTILE(2, 2);

#pragma unroll 1
    for (int it = 0; it < nk; it++) {
        const int st  = it & (NSTG - 1);
        const int rem = nk - 1 - it;
        if (rem >= 2)      CP_WAIT(2);
        else if (rem == 1) CP_WAIT(1);
        else               CP_WAIT(0);
        __syncthreads();

        const uint32_t* Asf = (const uint32_t*)(sm + st * ABUF);
        const uint32_t* Bsf = (const uint32_t*)(sm + NSTG * ABUF + st * BBUF);

#pragma unroll
        for (int ks = 0; ks < 2; ks++) {
            const int kb = ks * 8;
            uint32_t af[2][4];
#pragma unroll
            for (int mf = 0; mf < 2; mf++) {
                const int mrow = warpM * 32 + mf * 16 + r;
                af[mf][0] = Asf[mrow * 20 + kb + cq];
                af[mf][1] = Asf[(mrow + 8) * 20 + kb + cq];
                af[mf][2] = Asf[mrow * 20 + kb + cq + 4];
                af[mf][3] = Asf[(mrow + 8) * 20 + kb + cq + 4];
            }
#pragma unroll
            for (int nf = 0; nf < 8; nf++) {
                const int ncol = warpN * 64 + nf * 8 + r;
                uint32_t bfr[2];
                bfr[0] = Bsf[(kb + cq) * 136 + ncol];
                bfr[1] = Bsf[(kb + cq + 4) * 136 + ncol];
                mma8(acc[0][nf], af[0], bfr);
                mma8(acc[1][nf], af[1], bfr);
            }
        }

        if (it + 3 < nk) LOADTILE((it + 3) & (NSTG - 1), it + 3);
    }
#undef LOADTILE

#pragma unroll
    for (int mf = 0; mf < 2; mf++) {
#pragma unroll
        for (int nf = 0; nf < 8; nf++) {
            const int n = n0 + warpN * 64 + nf * 8 + 2 * cq;
            const float bx = bias[n], by = bias[n + 1];
#pragma unroll
            for (int half = 0; half < 2; half++) {
                const int m = m0 + warpM * 32 + mf * 16 + r + half * 8;
                float2 v = make_float2(acc[mf][nf][half * 2] + bx,
                                       acc[mf][nf][half * 2 + 1] + by);
                if (MODE == 0) {
                    v.x = rnaf(v.x);
                    v.y = rnaf(v.y);
                    const int which = n >> 10;
                    const int hh    = (n & 1023) >> 6;
                    const int d     = n & 63;
                    const int bb    = m >> 11;
                    const int t     = m & 2047;
                    if (which == 2) {
                        float* vt = g_vt + ((size_t)(bb * NH + hh) * HD) * TSEQ;
                        vt[(size_t)d * TSEQ + t]       = v.x;
                        vt[(size_t)(d + 1) * TSEQ + t] = v.y;
                    } else {
                        *(float2*)&g_qkv[which * (BSZ * NH * TSEQ * HD) +
                                         ((bb * NH + hh) * TSEQ + t) * HD + d] = v;
                    }
                } else {
                    *(float2*)&out[(size_t)m * N + n] = v;
                }
            }
        }
    }
}

// ===========================================================================
// FA2-style flash attention. K/V staged via cp.async (raw tf32-bit copies —
// V already transposed in gmem), 3-stage pipeline, 1 barrier/iter.
// R15 FIX: __syncthreads() between the tid==0 write of sA[] and its read
// (R14 dropped this barrier -> race -> wrong FIRE coefficients).
// ===========================================================================
#define TSK    64
#define KVB    (64 * 68)
#define AT_VT  (3 * KVB)
#define AT_W   (AT_VT + 3 * KVB)
#define ASMEM  ((AT_W + 104) * 4)

__device__ __forceinline__ float fire_mlp(float nd, const float* sw1,
                                          const float* sb1, const float* sw2) {
    float acc = 0.0f;
#pragma unroll
    for (int w = 0; w < MLPW; w++)
        acc = fmaf(fmaxf(fmaf(nd, sw1[w], sb1[w]), 0.0f), sw2[w], acc);
    return acc;
}

__global__ __launch_bounds__(256) void attn_mma(
        const float* __restrict__ w1, const float* __restrict__ b1,
        const float* __restrict__ w2) {
    extern __shared__ float af_[];
    float* Ksm = af_;            // [3][key 64][68]
    float* Vtm = af_ + AT_VT;    // [3][d 64][68]
    float* sw1 = af_ + AT_W;
    float* sb1 = sw1 + MLPW;
    float* sw2 = sb1 + MLPW;
    float* sA  = sw2 + MLPW;

    const int tid  = threadIdx.x;
    const int lane = tid & 31;
    const int warp = tid >> 5;
    const int h    = blockIdx.y;
    const int b    = blockIdx.z;
    const int q0   = (gridDim.x - 1 - blockIdx.x) * 128;
    const int tw   = q0 + warp * 16;
    const int r    = lane >> 2;
    const int cq   = lane & 3;
    const int t0   = tw + r;
    const int t1   = t0 + 8;

    if (tid < MLPW) {
        sw1[tid] = w1[tid];
        sb1[tid] = b1[tid];
        sw2[tid] = w2[tid * NH + h];
    }
    __syncthreads();
    if (tid == 0) {
        bool  lin = true;
        float a   = 0.0f;
#pragma unroll
        for (int w = 0; w < MLPW; w++) {
            lin = lin && (sb1[w] == 0.0f);
            a   = fmaf(fmaxf(sw1[w], 0.0f), sw2[w], a);
        }
        sA[0] = a;
        sA[1] = lin ? 1.0f : 0.0f;
    }

    const float invP0 = g_invP[t0];
    const float invP1 = g_invP[t1];

    const float* Qg  = g_qkv + (size_t)(b * NH + h) * TSEQ * HD;
    const float* Kg  = Qg + (size_t)BSZ * NH * TSEQ * HD;
    const float* Vtg = g_vt + (size_t)(b * NH + h) * HD * TSEQ;

    const float qsc = 0.125f * LOG2E;
    uint32_t qa[8][4];
#pragma unroll
    for (int kf = 0; kf < 8; kf++) {
        qa[kf][0] = f2tf32(Qg[(size_t)t0 * HD + kf * 8 + cq] * qsc);
        qa[kf][1] = f2tf32(Qg[(size_t)t1 * HD + kf * 8 + cq] * qsc);
        qa[kf][2] = f2tf32(Qg[(size_t)t0 * HD + kf * 8 + cq + 4] * qsc);
        qa[kf][3] = f2tf32(Qg[(size_t)t1 * HD + kf * 8 + cq + 4] * qsc);
    }

    float o[8][4];
#pragma unroll
    for (int nd = 0; nd < 8; nd++)
#pragma unroll
        for (int i = 0; i < 4; i++) o[nd][i] = 0.0f;
    float m0 = -1e30f, m1 = -1e30f, l0 = 0.0f, l1 = 0.0f;

    const int  srow = tid >> 2;
    const int  sc0  = (tid & 3) * 4;
    const uint32_t ksb = smem_u32(Ksm);
    const uint32_t vsb = smem_u32(Vtm);

#define KV_CP(s0, bufi)                                                       \
    do {                                                                      \
        const uint32_t kd = ksb + (uint32_t)(bufi) * (KVB * 4) +              \
                            (uint32_t)(srow * 68) * 4;                        \
        const uint32_t vd = vsb + (uint32_t)(bufi) * (KVB * 4) +              \
                            (uint32_t)(srow * 68) * 4;                        \
        const float* ksrc = Kg + (size_t)((s0) + srow) * HD;                  \
        const float* vsrc = Vtg + (size_t)srow * TSEQ + (s0);                 \
        _Pragma("unroll")                                                     \
        for (int j = 0; j < 4; j++) {                                         \
            const int c = sc0 + 16 * j;                                       \
            CP_ASYNC16(kd + 4u * c, ksrc + c);                                \
            CP_ASYNC16(vd + 4u * c, vsrc + c);                                \
        }                                                                     \
        CP_COMMIT();                                                          \
    } while (0)

    const int nt = (q0 + 128) >> 6;
    KV_CP(0, 0);
    KV_CP(TSK, 1);

    // R15 FIX: order the tid==0 sA[] write before every thread's read.
    __syncthreads();

    const float alpha = sA[0];
    const int   lin   = (sA[1] != 0.0f);
    const float ai0   = alpha * invP0 * LOG2E;
    const float ai1   = alpha * invP1 * LOG2E;
    const float* ut   = g_ut2 + UPAD;

#pragma unroll 1
    for (int it = 0; it < nt; it++) {
        const int buf = it % 3;
        const int s0  = it * TSK;

        if (it + 1 < nt) CP_WAIT(1);
        else             CP_WAIT(0);
        __syncthreads();

        if (it + 2 < nt) KV_CP((it + 2) * TSK, (it + 2) % 3);

        if (s0 <= tw + 15) {
            const bool     msk = (s0 + TSK - 1) > tw;
            const uint32_t kb  = ksb + (uint32_t)buf * (KVB * 4);
            const uint32_t vb  = vsb + (uint32_t)buf * (KVB * 4);

            float s[8][4];
#pragma unroll
            for (int nf = 0; nf < 8; nf++)
                s[nf][0] = s[nf][1] = s[nf][2] = s[nf][3] = 0.0f;
#pragma unroll
            for (int kfp = 0; kfp < 4; kfp++) {
#pragma unroll
                for (int nf = 0; nf < 8; nf++) {
                    uint32_t bb[4];
                    const uint32_t addr = kb +
                        4u * ((uint32_t)(8 * nf + (lane & 7)) * 68u +
                              16u * kfp + 4u * (lane >> 3));
                    ldm_x4(bb[0], bb[1], bb[2], bb[3], addr);
                    mma8(s[nf], qa[2 * kfp], bb);
                    mma8(s[nf], qa[2 * kfp + 1], bb + 2);
                }
            }

            float mt0 = -1e30f, mt1 = -1e30f;
#pragma unroll
            for (int nf = 0; nf < 8; nf++) {
                const int k0    = s0 + nf * 8 + 2 * cq;
                const int rel00 = t0 - k0;
                const float u00 = __ldg(&ut[rel00]);
                const float u01 = __ldg(&ut[rel00 - 1]);
                const float u10 = __ldg(&ut[rel00 + 8]);
                const float u11 = __ldg(&ut[rel00 + 7]);
                if (lin) {
                    s[nf][0] = fmaf(ai0, u00, s[nf][0]);
                    s[nf][1] = fmaf(ai0, u01, s[nf][1]);
                    s[nf][2] = fmaf(ai1, u10, s[nf][2]);
                    s[nf][3] = fmaf(ai1, u11, s[nf][3]);
                } else {
                    s[nf][0] = fmaf(fire_mlp(u00 * invP0, sw1, sb1, sw2), LOG2E, s[nf][0]);
                    s[nf][1] = fmaf(fire_mlp(u01 * invP0, sw1, sb1, sw2), LOG2E, s[nf][1]);
                    s[nf][2] = fmaf(fire_mlp(u10 * invP1, sw1, sb1, sw2), LOG2E, s[nf][2]);
                    s[nf][3] = fmaf(fire_mlp(u11 * invP1, sw1, sb1, sw2), LOG2E, s[nf][3]);
                }
                if (msk) {
                    if (rel00 < 0)     s[nf][0] = -1e30f;
                    if (rel00 - 1 < 0) s[nf][1] = -1e30f;
                    if (rel00 + 8 < 0) s[nf][2] = -1e30f;
                    if (rel00 + 7 < 0) s[nf][3] = -1e30f;
                }
                mt0 = fmaxf(mt0, fmaxf(s[nf][0], s[nf][1]));
                mt1 = fmaxf(mt1, fmaxf(s[nf][2], s[nf][3]));
            }
            mt0 = fmaxf(mt0, __shfl_xor_sync(0xffffffffu, mt0, 1));
            mt0 = fmaxf(mt0, __shfl_xor_sync(0xffffffffu, mt0, 2));
            mt1 = fmaxf(mt1, __shfl_xor_sync(0xffffffffu, mt1, 1));
            mt1 = fmaxf(mt1, __shfl_xor_sync(0xffffffffu, mt1, 2));

            const float mn0 = fmaxf(m0, mt0);
            const float mn1 = fmaxf(m1, mt1);
            const float f0  = ex2(m0 - mn0);
            const float f1  = ex2(m1 - mn1);
            m0 = mn0; m1 = mn1;
            l0 *= f0;  l1 *= f1;
#pragma unroll
            for (int nd = 0; nd < 8; nd++) {
                o[nd][0] *= f0; o[nd][1] *= f0;
                o[nd][2] *= f1; o[nd][3] *= f1;
            }
#pragma unroll
            for (int nf = 0; nf < 8; nf++) {
                s[nf][0] = ex2(s[nf][0] - m0);
                s[nf][1] = ex2(s[nf][1] - m0);
                s[nf][2] = ex2(s[nf][2] - m1);
                s[nf][3] = ex2(s[nf][3] - m1);
                l0 += s[nf][0] + s[nf][1];
                l1 += s[nf][2] + s[nf][3];
            }

            const int src1 = (lane & 28) | (cq >> 1);
            const int src2 = src1 + 2;
#pragma unroll
            for (int kf2 = 0; kf2 < 8; kf2++) {
                const float x0 = __shfl_sync(0xffffffffu, s[kf2][0], src1);
                const float x1 = __shfl_sync(0xffffffffu, s[kf2][1], src1);
                const float y0 = __shfl_sync(0xffffffffu, s[kf2][0], src2);
                const float y1 = __shfl_sync(0xffffffffu, s[kf2][1], src2);
                const float x2 = __shfl_sync(0xffffffffu, s[kf2][2], src1);
                const float x3 = __shfl_sync(0xffffffffu, s[kf2][3], src1);
                const float y2 = __shfl_sync(0xffffffffu, s[kf2][2], src2);
                const float y3 = __shfl_sync(0xffffffffu, s[kf2][3], src2);
                uint32_t pa[4];
                pa[0] = f2tf32((cq & 1) ? x1 : x0);
                pa[1] = f2tf32((cq & 1) ? x3 : x2);
                pa[2] = f2tf32((cq & 1) ? y1 : y0);
                pa[3] = f2tf32((cq & 1) ? y3 : y2);
#pragma unroll
                for (int g = 0; g < 4; g++) {
                    uint32_t bv[4];
                    const uint32_t addr = vb +
                        4u * ((uint32_t)(8 * (2 * g + (lane >> 4)) + (lane & 7)) * 68u +
                              8u * kf2 + 4u * ((lane >> 3) & 1));
                    ldm_x4(bv[0], bv[1], bv[2], bv[3], addr);
                    mma8(o[2 * g], pa, bv);
                    mma8(o[2 * g + 1], pa, bv + 2);
                }
            }
        }
        __syncthreads();
    }
#undef KV_CP

    l0 += __shfl_xor_sync(0xffffffffu, l0, 1);
    l0 += __shfl_xor_sync(0xffffffffu, l0, 2);
    l1 += __shfl_xor_sync(0xffffffffu, l1, 1);
    l1 += __shfl_xor_sync(0xffffffffu, l1, 2);
    const float inv0 = 1.0f / l0;
    const float inv1 = 1.0f / l1;
    float* y0p = &g_y[((size_t)(b * TSEQ) + t0) * CDIM + h * HD];
    float* y1p = &g_y[((size_t)(b * TSEQ) + t1) * CDIM + h * HD];
#pragma unroll
    for (int nd = 0; nd < 8; nd++) {
        const int d = nd * 8 + 2 * cq;
        *(float2*)&y0p[d] = make_float2(rnaf(o[nd][0] * inv0), rnaf(o[nd][1] * inv0));
        *(float2*)&y1p[d] = make_float2(rnaf(o[nd][2] * inv1), rnaf(o[nd][3] * inv1));
    }
}

// ===========================================================================
// Launch
// ===========================================================================
extern "C" void kernel_launch(void* const* d_in, const int* in_sizes, int n_in,
                              void* d_out, int out_size) {
    const float* x     = (const float*)d_in[0];
    const float* Wqkv  = (const float*)d_in[1];
    const float* bqkv  = (const float*)d_in[2];
    const float* Wproj = (const float*)d_in[3];
    const float* bproj = (const float*)d_in[4];
    const float* w1    = (const float*)d_in[5];
    const float* b1    = (const float*)d_in[6];
    const float* w2    = (const float*)d_in[7];
    const float* cpar  = (const float*)d_in[9];
    const float* lmul  = (const float*)d_in[10];
    float* out = (float*)d_out;

    cudaFuncSetAttribute(mma_gemm<0>,
                         cudaFuncAttributeMaxDynamicSharedMemorySize, GSMEM);
    cudaFuncSetAttribute(mma_gemm<1>,
                         cudaFuncAttributeMaxDynamicSharedMemorySize, GSMEM);
    cudaFuncSetAttribute(attn_mma,
                         cudaFuncAttributeMaxDynamicSharedMemorySize, ASMEM);

    float *xr, *wqkvr, *wprojr, *gy_ptr;
    cudaGetSymbolAddress((void**)&xr, g_xr);
    cudaGetSymbolAddress((void**)&wqkvr, g_wqkvr);
    cudaGetSymbolAddress((void**)&wprojr, g_wprojr);
    cudaGetSymbolAddress((void**)&gy_ptr, g_y);

    init_tables<<<(TSEQ + UPAD + 255) / 256, 256>>>(cpar, lmul);

    const int nx = BSZ * TSEQ * CDIM / 4;
    const int nq = CDIM * 3 * CDIM / 4;
    const int np = CDIM * CDIM / 4;
    cvt_tf32<<<(nx + 255) / 256, 256>>>((const float4*)x, (float4*)xr, nx);
    cvt_tf32<<<(nq + 255) / 256, 256>>>((const float4*)Wqkv, (float4*)wqkvr, nq);
    cvt_tf32<<<(np + 255) / 256, 256>>>((const float4*)Wproj, (float4*)wprojr, np);

    mma_gemm<0><<<dim3(3 * CDIM / 128, BSZ * TSEQ / 128), 256, GSMEM>>>(
        xr, wqkvr, bqkv, nullptr, CDIM, 3 * CDIM);

    attn_mma<<<dim3(TSEQ / 128, NH, BSZ), 256, ASMEM>>>(w1, b1, w2);

    mma_gemm<1><<<dim3(CDIM / 128, BSZ * TSEQ / 128), 256, GSMEM>>>(
        gy_ptr, wprojr, bproj, out, CDIM, CDIM);
}